// round 17
// baseline (speedup 1.0000x reference)
#include <cuda_runtime.h>
#include <math.h>
#include <stdint.h>

// Problem constants
#define NSPH 7
#define NRAD 6
#define ROW  48          // padded rbf row (42 used), 192 bytes
#define CAP_E 1048576    // capacity for edges (E = 1,000,000)

// Scratch (static device arrays; no allocation)
__device__ float g_rbf[(size_t)CAP_E * ROW];   // indexed by SORTED position
__device__ int   g_inv [CAP_E];                // edge -> sorted pos
__device__ float g_dist_sorted[CAP_E];         // dist in sorted order
__device__ unsigned g_hist[256];               // zero-init at load; self-rezero
__device__ unsigned g_off[256];
__device__ unsigned g_hist_done;               // zero-init; self-rezero
__device__ int   g_idx_is64;

// sqrt((2l+1)/(4*pi)) in double, rounded to f32 (matches numpy cast)
__device__ __constant__ float c_coef[NSPH] = {
    (float)0.28209479177387814,
    (float)0.48860251190291992,
    (float)0.63078313050504009,
    (float)0.74635266518023078,
    (float)0.84628437532163443,
    (float)0.93560257962738882,
    (float)1.01710723628205748
};

// tiers: arg < th -> bit-exact DP; [th, th2) -> accurate sincosf; else MUFU
__device__ __constant__ float c_th [NSPH] = {0.0f, 0.0f, 0.45f, 0.85f, 1.30f, 1.75f, 2.20f};
__device__ __constant__ float c_th2[NSPH] = {0.0f, 0.50f, 1.25f, 1.70f, 2.20f, 2.75f, 3.30f};

// ===========================================================================
// glibc scalar sinf/cosf port (bit-exact vs reference, round 9 rel_err==0)
// ===========================================================================
#define GSC_HPI_INV 0x1.45F306DC9C883p-1
#define GSC_HPI     0x1.921FB54442D18p0
#define GSC_C0  (1.0)
#define GSC_C1  (-0x1.ffffffd0c621cp-2)
#define GSC_C2  ( 0x1.55553e1068f19p-5)
#define GSC_C3  (-0x1.6c087e89a359dp-10)
#define GSC_C4  ( 0x1.99343027bf8c3p-16)
#define GSC_S1  (-0x1.555545995a603p-3)
#define GSC_S2  ( 0x1.1107605230bc4p-7)
#define GSC_S3  (-0x1.994eb3774cf24p-13)

__device__ __forceinline__ unsigned gsc_abstop12(float y) {
    return (__float_as_uint(y) >> 20) & 0x7ffu;
}
__device__ __forceinline__ double gsc_sinpoly(double x, double x2) {
    double x3 = x * x2;
    double s1 = fma(x2, GSC_S3, GSC_S2);
    double x7 = x3 * x2;
    double s  = fma(x3, GSC_S1, x);
    return fma(x7, s1, s);
}
__device__ __forceinline__ double gsc_cospoly(double x2) {
    double x4 = x2 * x2;
    double c2 = fma(x2, GSC_C4, GSC_C3);
    double c1 = fma(x2, GSC_C1, GSC_C0);
    double x6 = x4 * x2;
    double c  = fma(x4, GSC_C2, c1);
    return fma(x6, c2, c);
}
__device__ __forceinline__ float fneg_if(float v, bool neg) {
    return __uint_as_float(__float_as_uint(v) ^ (neg ? 0x80000000u : 0u));
}
__device__ __forceinline__ void gsc_sincosf2(float y, float* sp, float* cp) {
    double x = (double)y;
    unsigned at = gsc_abstop12(y);
    if (at < 0x3f4u) {
        if (at < 0x398u) { *sp = y; *cp = 1.0f; return; }
        double x2 = x * x;
        *sp = (float)gsc_sinpoly(x, x2);
        *cp = (float)gsc_cospoly(x2);
        return;
    }
    double r  = x * GSC_HPI_INV;
    double rd = rint(r);
    int    n  = (int)rd;
    x = fma(-rd, GSC_HPI, x);
    double x2 = x * x;
    float sv = (float)gsc_sinpoly(x, x2);
    float cv = (float)gsc_cospoly(x2);
    bool odd  = (n & 1) != 0;
    bool flip = (n & 2) != 0;
    if (!odd) { *sp = fneg_if(sv, flip); *cp = fneg_if(cv, flip); }
    else      { *sp = fneg_if(cv, flip); *cp = fneg_if(sv, !flip); }
}

// ---------------------------------------------------------------------------
// Launch 0: histogram + (last block) exclusive scan + self-rezero for replay
// g_hist / g_hist_done are zero at first run (static init) and re-zeroed by
// the last block each run -> graph-replay safe.
// ---------------------------------------------------------------------------
__device__ __forceinline__ int dist_bin(float d) {
    int b = (int)((d - 0.1f) * (256.0f / 4.9f));
    return min(255, max(0, b));
}
__global__ void hist_scan_kernel(const float* __restrict__ dist, int E) {
    __shared__ unsigned h[256];
    __shared__ bool last;
    int t = threadIdx.x;
    h[t] = 0u;
    __syncthreads();
    for (int i = blockIdx.x * blockDim.x + t; i < E; i += gridDim.x * blockDim.x)
        atomicAdd(&h[dist_bin(dist[i])], 1u);
    __syncthreads();
    if (h[t]) atomicAdd(&g_hist[t], h[t]);
    __threadfence();
    __syncthreads();
    if (t == 0) {
        unsigned prev = atomicAdd(&g_hist_done, 1u);
        last = (prev == gridDim.x - 1);
    }
    __syncthreads();
    if (last) {
        __shared__ unsigned tmp[256];
        unsigned own = g_hist[t];
        tmp[t] = own;
        __syncthreads();
        for (int off = 1; off < 256; off <<= 1) {
            unsigned v = tmp[t];
            __syncthreads();
            if (t >= off) v += tmp[t - off];
            __syncthreads();
            tmp[t] = v;
            __syncthreads();
        }
        g_off[t] = tmp[t] - own;
        // re-zero for next graph replay
        g_hist[t] = 0u;
        if (t == 0) g_hist_done = 0u;
    }
}

// ---------------------------------------------------------------------------
// Launch 1: scatter -> g_inv, g_dist_sorted ; block 0 also probes idx dtype
// ---------------------------------------------------------------------------
__global__ void scatter_kernel(const float* __restrict__ dist,
                               const int* __restrict__ idx32,
                               int n_check, int E) {
    if (blockIdx.x == 0) {
        __shared__ int any_nz;
        if (threadIdx.x == 0) any_nz = 0;
        __syncthreads();
        for (int i = threadIdx.x; i < n_check; i += blockDim.x) {
            if (idx32[2 * i + 1] != 0) any_nz = 1;
        }
        __syncthreads();
        if (threadIdx.x == 0) g_idx_is64 = (any_nz == 0) ? 1 : 0;
    }
    int i = blockIdx.x * blockDim.x + threadIdx.x;
    if (i >= E) return;
    float d = dist[i];
    unsigned pos = atomicAdd(&g_off[dist_bin(d)], 1u);
    g_inv[i] = (int)pos;
    g_dist_sorted[pos] = d;
}

// ---------------------------------------------------------------------------
// Launch 2: K1 per-edge rbf. Writes row at sorted position i, coalesced via
// shared staging. Three precision tiers (warp-coherent via dist sort).
// ---------------------------------------------------------------------------
#define K1_STRIDE 50
__global__ void __launch_bounds__(128) rbf_kernel(
    const float* __restrict__ zeros_lk,
    const float* __restrict__ norm_lk,
    int E)
{
    __shared__ float s_z [NSPH * NRAD];
    __shared__ float s_n [NSPH * NRAD];
    __shared__ float s_zi[NSPH * NRAD];
    __shared__ float s_stage[4][32 * K1_STRIDE];
    if (threadIdx.x < NSPH * NRAD) {
        float z = zeros_lk[threadIdx.x];
        s_z [threadIdx.x] = z;
        s_n [threadIdx.x] = norm_lk[threadIdx.x];
        s_zi[threadIdx.x] = __fdiv_rn(1.0f, z);
    }
    __syncthreads();

    int warp = threadIdx.x >> 5;
    int lane = threadIdx.x & 31;
    int i = blockIdx.x * 128 + threadIdx.x;
    float* st = &s_stage[warp][lane * K1_STRIDE];

    if (i < E) {
        float d = g_dist_sorted[i];            // coalesced
        float x = __fmul_rn(d, 0.2f);

        float x2  = __fmul_rn(x, x);
        float x4  = __fmul_rn(x2, x2);
        float xp0 = __fmul_rn(x4, x);

        float inv_x = __fdiv_rn(1.0f, x);
        float t2 = __fmul_rn(-28.0f, xp0);
        float t3 = __fmul_rn(__fmul_rn(48.0f, xp0), x);
        float t4 = __fmul_rn(__fmul_rn(__fmul_rn(-21.0f, xp0), x), x);
        float env = __fadd_rn(__fadd_rn(__fadd_rn(inv_x, t2), t3), t4);

        // l = 0: MUFU everywhere
        #pragma unroll
        for (int r = 0; r < NRAD; ++r) {
            float arg = __fmul_rn(x, s_z[r]);
            float inv = inv_x * s_zi[r];
            float j = __sinf(arg) * inv;
            st[r] = __fmul_rn(env, __fmul_rn(s_n[r], j));
        }
        // l = 1: accurate below th2, MUFU above
        {
            float th2 = c_th2[1];
            #pragma unroll
            for (int r = 0; r < NRAD; ++r) {
                float arg = __fmul_rn(x, s_z[NRAD + r]);
                float inv = inv_x * s_zi[NRAD + r];
                float s, c;
                if (arg < th2) sincosf(arg, &s, &c);
                else           __sincosf(arg, &s, &c);
                float j0 = s * inv;
                float j  = (j0 - c) * inv;
                st[NRAD + r] = __fmul_rn(env, __fmul_rn(s_n[NRAD + r], j));
            }
        }
        // l = 2..6: three tiers
        #pragma unroll 1
        for (int l = 2; l < NSPH; ++l) {
            float th  = c_th[l];
            float th2 = c_th2[l];
            #pragma unroll 1
            for (int r = 0; r < NRAD; ++r) {
                float arg = __fmul_rn(x, s_z[l * NRAD + r]);
                float j;
                if (arg < th) {
                    // exact reference path (bit-identical to round 9)
                    float s, c;
                    gsc_sincosf2(arg, &s, &c);
                    float j0 = __fdiv_rn(s, arg);
                    float jc = __fsub_rn(__fdiv_rn(s, __fmul_rn(arg, arg)),
                                         __fdiv_rn(c, arg));
                    float jm = j0;
                    for (int ii = 2; ii <= l; ++ii) {
                        float coef = __fdiv_rn((float)(2 * ii - 1), arg);
                        float jn = __fsub_rn(__fmul_rn(coef, jc), jm);
                        jm = jc; jc = jn;
                    }
                    j = jc;
                } else {
                    float inv = inv_x * s_zi[l * NRAD + r];
                    float s, c;
                    if (arg < th2) sincosf(arg, &s, &c);
                    else           __sincosf(arg, &s, &c);
                    float j0 = s * inv;
                    float jc = (j0 - c) * inv;
                    float jm = j0;
                    #pragma unroll
                    for (int ii = 2; ii <= 6; ++ii) {
                        if (ii > l) break;
                        float jn = fmaf((float)(2 * ii - 1) * inv, jc, -jm);
                        jm = jc; jc = jn;
                    }
                    j = jc;
                }
                st[l * NRAD + r] = __fmul_rn(env, __fmul_rn(s_n[l * NRAD + r], j));
            }
        }
        st[42] = 0.f; st[43] = 0.f; st[44] = 0.f; st[45] = 0.f;
        st[46] = 0.f; st[47] = 0.f;
    }
    __syncwarp();

    int warp_row0 = blockIdx.x * 128 + warp * 32;
    int nrows = E - warp_row0;
    if (nrows <= 0) return;
    if (nrows > 32) nrows = 32;
    float* gbase = g_rbf + (size_t)warp_row0 * ROW;
    #pragma unroll
    for (int it = 0; it < 24; ++it) {
        int k = it * 32 + lane;
        int rowl = k / 24;
        int col2 = k % 24;
        if (rowl < nrows) {
            float2 v = *reinterpret_cast<float2*>(
                &s_stage[warp][rowl * K1_STRIDE + col2 * 2]);
            *reinterpret_cast<float2*>(gbase + rowl * ROW + col2 * 2) = v;
        }
    }
}

// ---------------------------------------------------------------------------
// Launch 3: K2 per-triplet gather + Legendre * coef (PROFILING TARGET).
// Coalesced stores via shared staging; MUFU cos (Legendre amp <= 21).
// ---------------------------------------------------------------------------
#define K2_STRIDE 46
__global__ void __launch_bounds__(128) out_kernel(
    const float* __restrict__ angle,
    const int* __restrict__ idx32,
    float* __restrict__ out,
    int T)
{
    __shared__ float s_o[4][32 * K2_STRIDE];   // 4 warps * 5888B = 23.5KB

    int warp = threadIdx.x >> 5;
    int lane = threadIdx.x & 31;
    int t = blockIdx.x * 128 + threadIdx.x;
    float* st = &s_o[warp][lane * K2_STRIDE];

    if (t < T) {
        int e = g_idx_is64 ? __ldg(&idx32[2 * t]) : __ldg(&idx32[t]);
        int pos = __ldg(&g_inv[e]);

        float ct = __cosf(__ldg(&angle[t]));   // MUFU; Legendre amp <= 21
        float P0 = 1.0f;
        float P1 = ct;
        float P2 = __fmul_rn(__fsub_rn(__fmul_rn(__fmul_rn(3.0f,  ct), P1), P0),                   0.5f);
        float P3 = __fmul_rn(__fsub_rn(__fmul_rn(__fmul_rn(5.0f,  ct), P2), __fmul_rn(2.0f, P1)), 0.33333334f);
        float P4 = __fmul_rn(__fsub_rn(__fmul_rn(__fmul_rn(7.0f,  ct), P3), __fmul_rn(3.0f, P2)), 0.25f);
        float P5 = __fmul_rn(__fsub_rn(__fmul_rn(__fmul_rn(9.0f,  ct), P4), __fmul_rn(4.0f, P3)), 0.2f);
        float P6 = __fmul_rn(__fsub_rn(__fmul_rn(__fmul_rn(11.0f, ct), P5), __fmul_rn(5.0f, P4)), 0.16666667f);

        float cbf[NSPH];
        cbf[0] = __fmul_rn(P0, c_coef[0]);
        cbf[1] = __fmul_rn(P1, c_coef[1]);
        cbf[2] = __fmul_rn(P2, c_coef[2]);
        cbf[3] = __fmul_rn(P3, c_coef[3]);
        cbf[4] = __fmul_rn(P4, c_coef[4]);
        cbf[5] = __fmul_rn(P5, c_coef[5]);
        cbf[6] = __fmul_rn(P6, c_coef[6]);

        const float4* src = reinterpret_cast<const float4*>(
            g_rbf + (size_t)pos * ROW);
        #pragma unroll
        for (int q = 0; q < 10; ++q) {
            float4 f = __ldg(&src[q]);
            int k0 = 4 * q;
            st[k0 + 0] = __fmul_rn(f.x, cbf[(k0 + 0) / 6]);
            st[k0 + 1] = __fmul_rn(f.y, cbf[(k0 + 1) / 6]);
            st[k0 + 2] = __fmul_rn(f.z, cbf[(k0 + 2) / 6]);
            st[k0 + 3] = __fmul_rn(f.w, cbf[(k0 + 3) / 6]);
        }
        {
            float2 f = *reinterpret_cast<const float2*>(
                g_rbf + (size_t)pos * ROW + 40);
            st[40] = __fmul_rn(f.x, cbf[6]);
            st[41] = __fmul_rn(f.y, cbf[6]);
        }
        st[42] = 0.f; st[43] = 0.f; st[44] = 0.f; st[45] = 0.f;
    }
    __syncwarp();

    int warp_t0 = blockIdx.x * 128 + warp * 32;
    int nrows = T - warp_t0;
    if (nrows <= 0) return;
    if (nrows > 32) nrows = 32;
    float* gbase = out + (size_t)warp_t0 * 42;
    #pragma unroll
    for (int it = 0; it < 21; ++it) {
        int k = it * 32 + lane;
        int rowl = k / 21;
        int col2 = k % 21;
        if (rowl < nrows) {
            float2 v = *reinterpret_cast<float2*>(
                &s_o[warp][rowl * K2_STRIDE + col2 * 2]);
            *reinterpret_cast<float2*>(gbase + rowl * 42 + col2 * 2) = v;
        }
    }
}

// ---------------------------------------------------------------------------
// Launch
// ---------------------------------------------------------------------------
extern "C" void kernel_launch(void* const* d_in, const int* in_sizes, int n_in,
                              void* d_out, int out_size)
{
    const float* dist     = (const float*)d_in[0];
    const float* angle    = (const float*)d_in[1];
    const int*   idx32    = (const int*)  d_in[2];
    const float* zeros_lk = (const float*)d_in[3];
    const float* norm_lk  = (const float*)d_in[4];
    float* out = (float*)d_out;

    int E = in_sizes[0];
    int T = in_sizes[1];
    if (E > CAP_E) E = CAP_E;

    int n_check = 2048;
    if (2 * n_check > T) n_check = T / 2;

    hist_scan_kernel<<<296, 256>>>(dist, E);                          // 0
    scatter_kernel<<<(E + 255) / 256, 256>>>(dist, idx32, n_check, E);// 1
    rbf_kernel<<<(E + 127) / 128, 128>>>(zeros_lk, norm_lk, E);       // 2
    out_kernel<<<(T + 127) / 128, 128>>>(angle, idx32, out, T);       // 3
}